// round 12
// baseline (speedup 1.0000x reference)
#include <cuda_runtime.h>
#include <cuda_bf16.h>
#include <math.h>
#include <stdint.h>

// Problem constants
#define B_   8
#define LQ_  2048
#define LK_  2048
#define DIN_ 128
#define DO_  64
#define NROW (B_ * LQ_)   // 16384
#define LOG2E 1.4426950408889634f

typedef unsigned long long u64;

// ---- tensor-core + async primitives (baseline PTX, OK for plain sm_103) ---
__device__ __forceinline__ void ldsm_x4(uint32_t* r, uint32_t addr) {
    asm volatile("ldmatrix.sync.aligned.m8n8.x4.shared.b16 {%0,%1,%2,%3}, [%4];"
        : "=r"(r[0]), "=r"(r[1]), "=r"(r[2]), "=r"(r[3]) : "r"(addr));
}
__device__ __forceinline__ void mma16816(float* d, const uint32_t* a,
                                         uint32_t b0, uint32_t b1) {
    asm volatile(
        "mma.sync.aligned.m16n8k16.row.col.f32.bf16.bf16.f32 "
        "{%0,%1,%2,%3}, {%4,%5,%6,%7}, {%8,%9}, {%0,%1,%2,%3};"
        : "+f"(d[0]), "+f"(d[1]), "+f"(d[2]), "+f"(d[3])
        : "r"(a[0]), "r"(a[1]), "r"(a[2]), "r"(a[3]), "r"(b0), "r"(b1));
}
__device__ __forceinline__ uint32_t smem_u32(const void* p) {
    uint32_t a;
    asm("{ .reg .u64 t; cvta.to.shared.u64 t, %1; cvt.u32.u64 %0, t; }"
        : "=r"(a) : "l"(p));
    return a;
}
__device__ __forceinline__ void cp_async16(uint32_t dst, const void* src) {
    asm volatile("cp.async.ca.shared.global [%0], [%1], 16;"
                 :: "r"(dst), "l"(src) : "memory");
}
__device__ __forceinline__ void cp_async16_cg(uint32_t dst, const void* src) {
    asm volatile("cp.async.cg.shared.global [%0], [%1], 16;"
                 :: "r"(dst), "l"(src) : "memory");
}
#define CP_COMMIT()   asm volatile("cp.async.commit_group;" ::: "memory")
#define CP_WAIT_ALL() asm volatile("cp.async.wait_group 0;" ::: "memory")

__device__ __forceinline__ float ex2f(float x) {
    float y;
    asm("ex2.approx.ftz.f32 %0, %1;" : "=f"(y) : "f"(x));
    return y;
}

// pack two floats -> bf16x2 (lo = first memory element)
__device__ __forceinline__ uint32_t pkbf(float lo, float hi) {
    uint32_t r;
    asm("cvt.rn.bf16x2.f32 %0, %1, %2;" : "=r"(r) : "f"(hi), "f"(lo));
    return r;
}
__device__ __forceinline__ void split_pair(float x, float y,
                                           uint32_t& hp, uint32_t& lp) {
    hp = pkbf(x, y);
    float hx = __uint_as_float(hp << 16);
    float hy = __uint_as_float(hp & 0xFFFF0000u);
    lp = pkbf(x - hx, y - hy);
}

// ---- Scratch ---------------------------------------------------------------
__device__ __nv_bfloat16 g_qh[NROW * DO_];
__device__ __nv_bfloat16 g_ql[NROW * DO_];
__device__ __nv_bfloat16 g_kh[NROW * DO_];
__device__ __nv_bfloat16 g_kl[NROW * DO_];
__device__ __nv_bfloat16 g_vth[B_ * DO_ * LK_];   // [b][dim][key]
__device__ __nv_bfloat16 g_vtl[B_ * DO_ * LK_];
__device__ float g_po[2 * NROW * DO_];
__device__ float g_pl[2 * NROW];
__device__ int   g_flag[LQ_ / 128 * B_];          // 128 arrival counters

// ---------------------------------------------------------------------------
// Tensor-core projections. Grid 384 x 256 threads, 2 CTAs/SM.
// Path 0: Q (query * Wq * log2e).  Path 1: K.  Path 2: V (transposed out).
// ---------------------------------------------------------------------------
#define RSA 272
#define PR_AH 0
#define PR_AL (128 * RSA)
#define PR_WH (2 * 128 * RSA)
#define PR_WL (PR_WH + 64 * RSA)
#define PR_SMEM (PR_WL + 64 * RSA)   // 104448

__global__ __launch_bounds__(256, 2) void proj_mma_kernel(
    const float* __restrict__ query, const float* __restrict__ key,
    const float* __restrict__ Wq, const float* __restrict__ Wk,
    const float* __restrict__ Wv,
    __nv_bfloat16* __restrict__ oqh, __nv_bfloat16* __restrict__ oql,
    __nv_bfloat16* __restrict__ okh, __nv_bfloat16* __restrict__ okl,
    __nv_bfloat16* __restrict__ ovh, __nv_bfloat16* __restrict__ ovl)
{
    extern __shared__ __align__(16) char sm[];
    const uint32_t sb = smem_u32(sm);

    const int tid = threadIdx.x;
    const int w = tid >> 5;
    const int lane = tid & 31;
    const int path = blockIdx.x >> 7;          // 0=Q, 1=K, 2=V
    const size_t row0 = (size_t)(blockIdx.x & 127) * 128;
    const float* A = (path == 0) ? query : key;
    const float* W = (path == 0) ? Wq : (path == 1) ? Wk : Wv;
    // Q path: fold log2e into W so attention scores are log2-domain.
    const float wscale = (path == 0) ? LOG2E : 1.0f;

    // ---- stage A (fp32 -> bf16 hi/lo), coalesced ----
#pragma unroll 8
    for (int n = 0; n < 32; n++) {
        int idx = tid + n * 256;
        int r = idx >> 6, c = idx & 63;
        float2 a = ((const float2*)A)[(row0 + r) * (DIN_ / 2) + c];
        uint32_t hp, lp;
        split_pair(a.x, a.y, hp, lp);
        *(uint32_t*)(sm + PR_AH + r * RSA + c * 4) = hp;
        *(uint32_t*)(sm + PR_AL + r * RSA + c * 4) = lp;
    }
    // ---- stage W^T hi/lo (scaled) ----
#pragma unroll 8
    for (int n = 0; n < 32; n++) {
        int idx = tid + n * 256;
        int k = idx >> 6, c = idx & 63;
        float v = W[k * DO_ + c] * wscale;
        __nv_bfloat16 h = __float2bfloat16(v);
        __nv_bfloat16 l = __float2bfloat16(v - __bfloat162float(h));
        *(__nv_bfloat16*)(sm + PR_WH + c * RSA + k * 2) = h;
        *(__nv_bfloat16*)(sm + PR_WL + c * RSA + k * 2) = l;
    }
    __syncthreads();

    // ---- warp m16 x n64 split-bf16 GEMM over K=128 ----
    float sacc[8][4];
#pragma unroll
    for (int j = 0; j < 8; j++)
#pragma unroll
        for (int c = 0; c < 4; c++) sacc[j][c] = 0.f;

    const uint32_t a_base = sb + PR_AH +
        (uint32_t)((16 * w + (lane & 15)) * RSA + (lane >> 4) * 16);
    const uint32_t b_off = (uint32_t)((lane & 15) * RSA + (lane >> 4) * 16);

#pragma unroll
    for (int g = 0; g < 8; g++) {
        uint32_t ah[4], al[4];
        ldsm_x4(ah, a_base + 32 * g);
        ldsm_x4(al, a_base + (PR_AL - PR_AH) + 32 * g);
#pragma unroll
        for (int j2 = 0; j2 < 4; j2++) {
            uint32_t bh[4], bl[4];
            uint32_t ba = sb + PR_WH + j2 * (16 * RSA) + b_off + 32 * g;
            ldsm_x4(bh, ba);
            ldsm_x4(bl, ba + (PR_WL - PR_WH));
#pragma unroll
            for (int js = 0; js < 2; js++) {
                float* acc = sacc[2 * j2 + js];
                mma16816(acc, ah, bh[js], bh[js + 2]);
                mma16816(acc, ah, bl[js], bl[js + 2]);
                mma16816(acc, al, bh[js], bh[js + 2]);
            }
        }
    }

    if (path < 2) {
        __nv_bfloat16* oh = (path == 0) ? oqh : okh;
        __nv_bfloat16* ol = (path == 0) ? oql : okl;
        int r0 = 16 * w + (lane >> 2);
#pragma unroll
        for (int j = 0; j < 8; j++) {
            int c0 = 8 * j + (lane & 3) * 2;
            uint32_t hp, lp;
            split_pair(sacc[j][0], sacc[j][1], hp, lp);
            *(uint32_t*)&oh[(row0 + r0) * DO_ + c0] = hp;
            *(uint32_t*)&ol[(row0 + r0) * DO_ + c0] = lp;
            split_pair(sacc[j][2], sacc[j][3], hp, lp);
            *(uint32_t*)&oh[(row0 + r0 + 8) * DO_ + c0] = hp;
            *(uint32_t*)&ol[(row0 + r0 + 8) * DO_ + c0] = lp;
        }
    } else {
        // V: transpose via smem (reuse A region), coalesced uint4 out
        __syncthreads();
        int key0 = 16 * w + (lane >> 2);
#pragma unroll
        for (int j = 0; j < 8; j++) {
            int c0 = 8 * j + (lane & 3) * 2;
            uint32_t hp, lp;
            split_pair(sacc[j][0], sacc[j][1], hp, lp);
            *(__nv_bfloat16*)(sm + PR_AH + c0 * RSA + key0 * 2) =
                __ushort_as_bfloat16((unsigned short)(hp & 0xFFFF));
            *(__nv_bfloat16*)(sm + PR_AH + (c0 + 1) * RSA + key0 * 2) =
                __ushort_as_bfloat16((unsigned short)(hp >> 16));
            *(__nv_bfloat16*)(sm + PR_AL + c0 * RSA + key0 * 2) =
                __ushort_as_bfloat16((unsigned short)(lp & 0xFFFF));
            *(__nv_bfloat16*)(sm + PR_AL + (c0 + 1) * RSA + key0 * 2) =
                __ushort_as_bfloat16((unsigned short)(lp >> 16));
            split_pair(sacc[j][2], sacc[j][3], hp, lp);
            *(__nv_bfloat16*)(sm + PR_AH + c0 * RSA + (key0 + 8) * 2) =
                __ushort_as_bfloat16((unsigned short)(hp & 0xFFFF));
            *(__nv_bfloat16*)(sm + PR_AH + (c0 + 1) * RSA + (key0 + 8) * 2) =
                __ushort_as_bfloat16((unsigned short)(hp >> 16));
            *(__nv_bfloat16*)(sm + PR_AL + c0 * RSA + (key0 + 8) * 2) =
                __ushort_as_bfloat16((unsigned short)(lp & 0xFFFF));
            *(__nv_bfloat16*)(sm + PR_AL + (c0 + 1) * RSA + (key0 + 8) * 2) =
                __ushort_as_bfloat16((unsigned short)(lp >> 16));
        }
        __syncthreads();
        const size_t bb = row0 >> 11;
        const int k0 = (int)(row0 & 2047);
#pragma unroll
        for (int n = 0; n < 4; n++) {
            int idx = tid + n * 256;
            int d = idx >> 4, c = idx & 15;
            uint4 vh = *(const uint4*)(sm + PR_AH + d * RSA + c * 16);
            uint4 vl = *(const uint4*)(sm + PR_AL + d * RSA + c * 16);
            size_t dst = (bb * DO_ + d) * (size_t)LK_ + k0 + c * 8;
            *(uint4*)&ovh[dst] = vh;
            *(uint4*)&ovl[dst] = vl;
        }
    }
}

// ---------------------------------------------------------------------------
// mma.sync flash attention + fused split-K reduce.
// BQ=128, 4 warps (m32 x n64), key-split x2, second-arriving CTA reduces.
// ---------------------------------------------------------------------------
#define RSTRIDE 144
#define TILE_B  (64 * RSTRIDE)
#define QTILE_B (128 * RSTRIDE)
#define O_QH  0
#define O_QL  QTILE_B
#define O_KV  (2 * QTILE_B)
#define KVBUF (4 * TILE_B)
#define SM_BYTES (O_KV + 2 * KVBUF)   // 110592

__device__ __forceinline__ void kv_load(
    uint32_t dstbase, int tid, int b, int kt,
    const __nv_bfloat16* __restrict__ kh, const __nv_bfloat16* __restrict__ kl,
    const __nv_bfloat16* __restrict__ vth, const __nv_bfloat16* __restrict__ vtl)
{
#pragma unroll
    for (int n = 0; n < 16; n++) {
        int i = tid + n * 128;
        int t = i >> 9, r = (i >> 3) & 63, c = i & 7;
        const __nv_bfloat16* src;
        if (t == 0)      src = kh  + ((size_t)b * LK_ + kt + r) * DO_ + c * 8;
        else if (t == 1) src = kl  + ((size_t)b * LK_ + kt + r) * DO_ + c * 8;
        else if (t == 2) src = vth + ((size_t)b * DO_ + r) * LK_ + kt + c * 8;
        else             src = vtl + ((size_t)b * DO_ + r) * LK_ + kt + c * 8;
        cp_async16_cg(dstbase + t * TILE_B + r * RSTRIDE + c * 16, src);
    }
}

__global__ __launch_bounds__(128, 2) void attn_mma_kernel(
    const __nv_bfloat16* __restrict__ qh, const __nv_bfloat16* __restrict__ ql,
    const __nv_bfloat16* __restrict__ kh, const __nv_bfloat16* __restrict__ kl,
    const __nv_bfloat16* __restrict__ vth, const __nv_bfloat16* __restrict__ vtl,
    float* __restrict__ po, float* __restrict__ pl,
    int* __restrict__ flag, float* __restrict__ out)
{
    extern __shared__ __align__(16) char sm[];
    const uint32_t sb = smem_u32(sm);

    const int tid = threadIdx.x;
    const int w = tid >> 5;
    const int lane = tid & 31;
    const int b = blockIdx.y;
    const int ks = blockIdx.z;
    const int it0 = ks * (LK_ / 128);
    const int it1 = it0 + (LK_ / 128);
    const size_t q0 = (size_t)blockIdx.x * 128;
    const int bi = b * (LQ_ / 128) + blockIdx.x;

#pragma unroll
    for (int n = 0; n < 16; n++) {
        int i = tid + n * 128;
        int t = i >> 10, r = (i >> 3) & 127, c = i & 7;
        const __nv_bfloat16* src =
            (t ? ql : qh) + ((size_t)b * LQ_ + q0 + r) * DO_ + c * 8;
        cp_async16(sb + (t ? O_QL : O_QH) + r * RSTRIDE + c * 16, src);
    }
    kv_load(sb + O_KV, tid, b, it0 * 64, kh, kl, vth, vtl);
    CP_COMMIT();
    CP_WAIT_ALL();
    __syncthreads();

    uint32_t qfh[2][4][4], qfl[2][4][4];
#pragma unroll
    for (int mi = 0; mi < 2; mi++) {
        int arow = 32 * w + 16 * mi + (lane & 7) + 8 * ((lane >> 3) & 1);
        int acol = 8 * (lane >> 4);
        uint32_t base = (uint32_t)(arow * RSTRIDE + acol * 2);
#pragma unroll
        for (int g = 0; g < 4; g++) {
            ldsm_x4(qfh[mi][g], sb + O_QH + base + 32 * g);
            ldsm_x4(qfl[mi][g], sb + O_QL + base + 32 * g);
        }
    }

    const uint32_t boff = (uint32_t)((lane & 7) * RSTRIDE + (lane >> 3) * 16);

    float oacc[2][8][4];
#pragma unroll
    for (int mi = 0; mi < 2; mi++)
#pragma unroll
        for (int j = 0; j < 8; j++)
#pragma unroll
            for (int c = 0; c < 4; c++) oacc[mi][j][c] = 0.f;
    float lsum[2][2] = {{0.f, 0.f}, {0.f, 0.f}};

    for (int it = it0; it < it1; it++) {
        const uint32_t kvb = sb + O_KV + (uint32_t)(it & 1) * KVBUF;
        if (it + 1 < it1) {
            kv_load(sb + O_KV + (uint32_t)((it + 1) & 1) * KVBUF,
                    tid, b, (it + 1) * 64, kh, kl, vth, vtl);
            CP_COMMIT();
        }

#pragma unroll 1
        for (int half = 0; half < 2; half++) {
            float sacc[2][4][4];
#pragma unroll
            for (int mi = 0; mi < 2; mi++)
#pragma unroll
                for (int jj = 0; jj < 4; jj++)
#pragma unroll
                    for (int c = 0; c < 4; c++) sacc[mi][jj][c] = 0.f;

#pragma unroll
            for (int jj = 0; jj < 4; jj++) {
                int j = 4 * half + jj;
                uint32_t bh[8], bl[8];
                uint32_t kb = kvb + j * (8 * RSTRIDE) + boff;
                ldsm_x4(bh, kb);
                ldsm_x4(bh + 4, kb + 64);
                uint32_t lb = kvb + TILE_B + j * (8 * RSTRIDE) + boff;
                ldsm_x4(bl, lb);
                ldsm_x4(bl + 4, lb + 64);
#pragma unroll
                for (int mi = 0; mi < 2; mi++)
#pragma unroll
                    for (int s = 0; s < 4; s++) {
                        mma16816(sacc[mi][jj], qfh[mi][s], bh[2 * s], bh[2 * s + 1]);
                        mma16816(sacc[mi][jj], qfh[mi][s], bl[2 * s], bl[2 * s + 1]);
                        mma16816(sacc[mi][jj], qfl[mi][s], bh[2 * s], bh[2 * s + 1]);
                    }
            }

            // scores are log2-domain (Wq pre-scaled): exp = bare ex2
            uint32_t pfh[2][2][4], pfl[2][2][4];
#pragma unroll
            for (int mi = 0; mi < 2; mi++)
#pragma unroll
                for (int sg = 0; sg < 2; sg++) {
                    float p[8];
                    p[0] = ex2f(sacc[mi][2 * sg][0]);
                    p[1] = ex2f(sacc[mi][2 * sg][1]);
                    p[2] = ex2f(sacc[mi][2 * sg][2]);
                    p[3] = ex2f(sacc[mi][2 * sg][3]);
                    p[4] = ex2f(sacc[mi][2 * sg + 1][0]);
                    p[5] = ex2f(sacc[mi][2 * sg + 1][1]);
                    p[6] = ex2f(sacc[mi][2 * sg + 1][2]);
                    p[7] = ex2f(sacc[mi][2 * sg + 1][3]);
                    lsum[mi][0] += (p[0] + p[1]) + (p[4] + p[5]);
                    lsum[mi][1] += (p[2] + p[3]) + (p[6] + p[7]);
#pragma unroll
                    for (int q = 0; q < 4; q++) {
                        uint32_t hp, lp;
                        split_pair(p[2 * q], p[2 * q + 1], hp, lp);
                        pfh[mi][sg][q] = hp;
                        pfl[mi][sg][q] = lp;
                    }
                }

#pragma unroll
            for (int j = 0; j < 8; j++) {
                uint32_t vh[4], vl[4];
                uint32_t vb = kvb + 2 * TILE_B + j * (8 * RSTRIDE) + half * 64 + boff;
                ldsm_x4(vh, vb);
                ldsm_x4(vl, vb + TILE_B);
#pragma unroll
                for (int mi = 0; mi < 2; mi++)
#pragma unroll
                    for (int sg = 0; sg < 2; sg++) {
                        mma16816(oacc[mi][j], pfh[mi][sg], vh[2 * sg], vh[2 * sg + 1]);
                        mma16816(oacc[mi][j], pfh[mi][sg], vl[2 * sg], vl[2 * sg + 1]);
                        mma16816(oacc[mi][j], pfl[mi][sg], vh[2 * sg], vh[2 * sg + 1]);
                    }
            }
        }

        CP_WAIT_ALL();
        __syncthreads();
    }

    // ---- write partial O + l ----
#pragma unroll
    for (int mi = 0; mi < 2; mi++) {
        float l0 = lsum[mi][0], l1 = lsum[mi][1];
        l0 += __shfl_xor_sync(0xffffffffu, l0, 1);
        l0 += __shfl_xor_sync(0xffffffffu, l0, 2);
        l1 += __shfl_xor_sync(0xffffffffu, l1, 1);
        l1 += __shfl_xor_sync(0xffffffffu, l1, 2);

        int row = 32 * w + 16 * mi + (lane >> 2);
        size_t rg = (size_t)b * LQ_ + q0 + row;
        float* ob = po + ((size_t)ks * NROW + rg) * DO_ + (lane & 3) * 2;
#pragma unroll
        for (int j = 0; j < 8; j++) {
            *(float2*)(ob + 8 * j) = make_float2(oacc[mi][j][0], oacc[mi][j][1]);
            *(float2*)(ob + 8 * j + 8 * DO_) = make_float2(oacc[mi][j][2], oacc[mi][j][3]);
        }
        if ((lane & 3) == 0) {
            pl[(size_t)ks * NROW + rg] = l0;
            pl[(size_t)ks * NROW + rg + 8] = l1;
        }
    }

    // ---- fused reduce: second-arriving CTA combines both halves ----
    __threadfence();
    __shared__ int s_old;
    __syncthreads();
    if (tid == 0) s_old = atomicAdd(&flag[bi], 1);
    __syncthreads();
    if (s_old == 1) {
        __threadfence();   // acquire side: peer's writes now visible
        const float4* P0 = (const float4*)po;
        const float4* P1 = P0 + (size_t)NROW * DO_ / 4;
        // 128 rows x 16 float4; 128 threads -> 16 each
#pragma unroll
        for (int n = 0; n < 16; n++) {
            int idx = tid + n * 128;          // float4 index within tile
            int r = idx >> 4, c = idx & 15;
            size_t rg = (size_t)b * LQ_ + q0 + r;
            float inv = 1.0f / (pl[rg] + pl[NROW + rg]);
            size_t gi = rg * (DO_ / 4) + c;
            float4 a = P0[gi];
            float4 bb = P1[gi];
            float4 rr = make_float4((a.x + bb.x) * inv, (a.y + bb.y) * inv,
                                    (a.z + bb.z) * inv, (a.w + bb.w) * inv);
            ((float4*)out)[gi] = rr;
        }
        __syncthreads();
        if (tid == 0) flag[bi] = 0;           // reset for next graph replay
    }
}

// ---------------------------------------------------------------------------
extern "C" void kernel_launch(void* const* d_in, const int* in_sizes, int n_in,
                              void* d_out, int out_size)
{
    const float* query = (const float*)d_in[0];
    const float* key   = (const float*)d_in[1];
    const float* Wq    = (const float*)d_in[2];
    const float* Wk    = (const float*)d_in[3];
    const float* Wv    = (const float*)d_in[4];
    float* out = (float*)d_out;

    __nv_bfloat16 *qh, *ql, *khp, *klp, *vth, *vtl;
    float *po, *pl;
    int* flag;
    cudaGetSymbolAddress((void**)&qh, g_qh);
    cudaGetSymbolAddress((void**)&ql, g_ql);
    cudaGetSymbolAddress((void**)&khp, g_kh);
    cudaGetSymbolAddress((void**)&klp, g_kl);
    cudaGetSymbolAddress((void**)&vth, g_vth);
    cudaGetSymbolAddress((void**)&vtl, g_vtl);
    cudaGetSymbolAddress((void**)&po, g_po);
    cudaGetSymbolAddress((void**)&pl, g_pl);
    cudaGetSymbolAddress((void**)&flag, g_flag);

    cudaFuncSetAttribute(proj_mma_kernel,
                         cudaFuncAttributeMaxDynamicSharedMemorySize, PR_SMEM);
    proj_mma_kernel<<<384, 256, PR_SMEM>>>(query, key, Wq, Wk, Wv,
                                           qh, ql, khp, klp, vth, vtl);

    cudaFuncSetAttribute(attn_mma_kernel,
                         cudaFuncAttributeMaxDynamicSharedMemorySize, SM_BYTES);
    dim3 grid(LQ_ / 128, B_, 2);
    attn_mma_kernel<<<grid, 128, SM_BYTES>>>(qh, ql, khp, klp, vth, vtl,
                                             po, pl, flag, out);
}

// round 13
// speedup vs baseline: 1.2459x; 1.2459x over previous
#include <cuda_runtime.h>
#include <cuda_bf16.h>
#include <cuda_fp16.h>
#include <math.h>
#include <stdint.h>

// Problem constants
#define B_   8
#define LQ_  2048
#define LK_  2048
#define DIN_ 128
#define DO_  64
#define NROW (B_ * LQ_)   // 16384
#define LOG2E 1.4426950408889634f

typedef unsigned long long u64;

// ---- tensor-core + async primitives (baseline PTX, OK for plain sm_103) ---
__device__ __forceinline__ void ldsm_x4(uint32_t* r, uint32_t addr) {
    asm volatile("ldmatrix.sync.aligned.m8n8.x4.shared.b16 {%0,%1,%2,%3}, [%4];"
        : "=r"(r[0]), "=r"(r[1]), "=r"(r[2]), "=r"(r[3]) : "r"(addr));
}
__device__ __forceinline__ void mma16816(float* d, const uint32_t* a,
                                         uint32_t b0, uint32_t b1) {
    asm volatile(
        "mma.sync.aligned.m16n8k16.row.col.f32.bf16.bf16.f32 "
        "{%0,%1,%2,%3}, {%4,%5,%6,%7}, {%8,%9}, {%0,%1,%2,%3};"
        : "+f"(d[0]), "+f"(d[1]), "+f"(d[2]), "+f"(d[3])
        : "r"(a[0]), "r"(a[1]), "r"(a[2]), "r"(a[3]), "r"(b0), "r"(b1));
}
__device__ __forceinline__ void mma16816_f16(float* d, const uint32_t* a,
                                             uint32_t b0, uint32_t b1) {
    asm volatile(
        "mma.sync.aligned.m16n8k16.row.col.f32.f16.f16.f32 "
        "{%0,%1,%2,%3}, {%4,%5,%6,%7}, {%8,%9}, {%0,%1,%2,%3};"
        : "+f"(d[0]), "+f"(d[1]), "+f"(d[2]), "+f"(d[3])
        : "r"(a[0]), "r"(a[1]), "r"(a[2]), "r"(a[3]), "r"(b0), "r"(b1));
}
__device__ __forceinline__ uint32_t smem_u32(const void* p) {
    uint32_t a;
    asm("{ .reg .u64 t; cvta.to.shared.u64 t, %1; cvt.u32.u64 %0, t; }"
        : "=r"(a) : "l"(p));
    return a;
}
__device__ __forceinline__ void cp_async16(uint32_t dst, const void* src) {
    asm volatile("cp.async.ca.shared.global [%0], [%1], 16;"
                 :: "r"(dst), "l"(src) : "memory");
}
__device__ __forceinline__ void cp_async16_cg(uint32_t dst, const void* src) {
    asm volatile("cp.async.cg.shared.global [%0], [%1], 16;"
                 :: "r"(dst), "l"(src) : "memory");
}
#define CP_COMMIT()   asm volatile("cp.async.commit_group;" ::: "memory")
#define CP_WAIT_ALL() asm volatile("cp.async.wait_group 0;" ::: "memory")

__device__ __forceinline__ float ex2f(float x) {
    float y;
    asm("ex2.approx.ftz.f32 %0, %1;" : "=f"(y) : "f"(x));
    return y;
}

// pack two floats -> bf16x2
__device__ __forceinline__ uint32_t pkbf(float lo, float hi) {
    uint32_t r;
    asm("cvt.rn.bf16x2.f32 %0, %1, %2;" : "=r"(r) : "f"(hi), "f"(lo));
    return r;
}
__device__ __forceinline__ void split_pair(float x, float y,
                                           uint32_t& hp, uint32_t& lp) {
    hp = pkbf(x, y);
    float hx = __uint_as_float(hp << 16);
    float hy = __uint_as_float(hp & 0xFFFF0000u);
    lp = pkbf(x - hx, y - hy);
}
__device__ __forceinline__ uint32_t pkhf(float x, float y) {
    __half2 h = __floats2half2_rn(x, y);
    return *(uint32_t*)&h;
}

// ---- Scratch ---------------------------------------------------------------
__device__ __nv_bfloat16 g_qh[NROW * DO_];
__device__ __nv_bfloat16 g_ql[NROW * DO_];
__device__ __nv_bfloat16 g_kh[NROW * DO_];
__device__ __nv_bfloat16 g_kl[NROW * DO_];
__device__ __half        g_vt[B_ * DO_ * LK_];    // [b][dim][key], fp16
__device__ float g_po[2 * NROW * DO_];
__device__ float g_pl[2 * NROW];
__device__ float g_pm[2 * NROW];
__device__ int   g_flag[LQ_ / 128 * B_];

// ---------------------------------------------------------------------------
// Tensor-core projections. Grid 384 x 256 threads, 2 CTAs/SM.
// Path 0: Q (query * Wq * log2e).  Path 1: K.  Path 2: V (fp16, transposed).
// ---------------------------------------------------------------------------
#define RSA 272
#define PR_AH 0
#define PR_AL (128 * RSA)
#define PR_WH (2 * 128 * RSA)
#define PR_WL (PR_WH + 64 * RSA)
#define PR_SMEM (PR_WL + 64 * RSA)   // 104448

__global__ __launch_bounds__(256, 2) void proj_mma_kernel(
    const float* __restrict__ query, const float* __restrict__ key,
    const float* __restrict__ Wq, const float* __restrict__ Wk,
    const float* __restrict__ Wv,
    __nv_bfloat16* __restrict__ oqh, __nv_bfloat16* __restrict__ oql,
    __nv_bfloat16* __restrict__ okh, __nv_bfloat16* __restrict__ okl,
    __half* __restrict__ ovt)
{
    extern __shared__ __align__(16) char sm[];
    const uint32_t sb = smem_u32(sm);

    const int tid = threadIdx.x;
    const int w = tid >> 5;
    const int lane = tid & 31;
    const int path = blockIdx.x >> 7;          // 0=Q, 1=K, 2=V
    const size_t row0 = (size_t)(blockIdx.x & 127) * 128;
    const float* A = (path == 0) ? query : key;
    const float* W = (path == 0) ? Wq : (path == 1) ? Wk : Wv;
    const float wscale = (path == 0) ? LOG2E : 1.0f;

    // ---- stage A (fp32 -> bf16 hi/lo), coalesced ----
#pragma unroll 8
    for (int n = 0; n < 32; n++) {
        int idx = tid + n * 256;
        int r = idx >> 6, c = idx & 63;
        float2 a = ((const float2*)A)[(row0 + r) * (DIN_ / 2) + c];
        uint32_t hp, lp;
        split_pair(a.x, a.y, hp, lp);
        *(uint32_t*)(sm + PR_AH + r * RSA + c * 4) = hp;
        *(uint32_t*)(sm + PR_AL + r * RSA + c * 4) = lp;
    }
    // ---- stage W^T hi/lo (scaled) ----
#pragma unroll 8
    for (int n = 0; n < 32; n++) {
        int idx = tid + n * 256;
        int k = idx >> 6, c = idx & 63;
        float v = W[k * DO_ + c] * wscale;
        __nv_bfloat16 h = __float2bfloat16(v);
        __nv_bfloat16 l = __float2bfloat16(v - __bfloat162float(h));
        *(__nv_bfloat16*)(sm + PR_WH + c * RSA + k * 2) = h;
        *(__nv_bfloat16*)(sm + PR_WL + c * RSA + k * 2) = l;
    }
    __syncthreads();

    // ---- warp m16 x n64 split-bf16 GEMM over K=128 ----
    float sacc[8][4];
#pragma unroll
    for (int j = 0; j < 8; j++)
#pragma unroll
        for (int c = 0; c < 4; c++) sacc[j][c] = 0.f;

    const uint32_t a_base = sb + PR_AH +
        (uint32_t)((16 * w + (lane & 15)) * RSA + (lane >> 4) * 16);
    const uint32_t b_off = (uint32_t)((lane & 15) * RSA + (lane >> 4) * 16);

#pragma unroll
    for (int g = 0; g < 8; g++) {
        uint32_t ah[4], al[4];
        ldsm_x4(ah, a_base + 32 * g);
        ldsm_x4(al, a_base + (PR_AL - PR_AH) + 32 * g);
#pragma unroll
        for (int j2 = 0; j2 < 4; j2++) {
            uint32_t bh[4], bl[4];
            uint32_t ba = sb + PR_WH + j2 * (16 * RSA) + b_off + 32 * g;
            ldsm_x4(bh, ba);
            ldsm_x4(bl, ba + (PR_WL - PR_WH));
#pragma unroll
            for (int js = 0; js < 2; js++) {
                float* acc = sacc[2 * j2 + js];
                mma16816(acc, ah, bh[js], bh[js + 2]);
                mma16816(acc, ah, bl[js], bl[js + 2]);
                mma16816(acc, al, bh[js], bh[js + 2]);
            }
        }
    }

    if (path < 2) {
        __nv_bfloat16* oh = (path == 0) ? oqh : okh;
        __nv_bfloat16* ol = (path == 0) ? oql : okl;
        int r0 = 16 * w + (lane >> 2);
#pragma unroll
        for (int j = 0; j < 8; j++) {
            int c0 = 8 * j + (lane & 3) * 2;
            uint32_t hp, lp;
            split_pair(sacc[j][0], sacc[j][1], hp, lp);
            *(uint32_t*)&oh[(row0 + r0) * DO_ + c0] = hp;
            *(uint32_t*)&ol[(row0 + r0) * DO_ + c0] = lp;
            split_pair(sacc[j][2], sacc[j][3], hp, lp);
            *(uint32_t*)&oh[(row0 + r0 + 8) * DO_ + c0] = hp;
            *(uint32_t*)&ol[(row0 + r0 + 8) * DO_ + c0] = lp;
        }
    } else {
        // V: fp16 single, transpose via smem (reuse A region), uint4 out
        __syncthreads();
        int key0 = 16 * w + (lane >> 2);
#pragma unroll
        for (int j = 0; j < 8; j++) {
            int c0 = 8 * j + (lane & 3) * 2;
            *(__half*)(sm + PR_AH + c0 * RSA + key0 * 2) = __float2half_rn(sacc[j][0]);
            *(__half*)(sm + PR_AH + (c0 + 1) * RSA + key0 * 2) = __float2half_rn(sacc[j][1]);
            *(__half*)(sm + PR_AH + c0 * RSA + (key0 + 8) * 2) = __float2half_rn(sacc[j][2]);
            *(__half*)(sm + PR_AH + (c0 + 1) * RSA + (key0 + 8) * 2) = __float2half_rn(sacc[j][3]);
        }
        __syncthreads();
        const size_t bb = row0 >> 11;
        const int k0 = (int)(row0 & 2047);
        // 64 dims x 16 uint4 (128 keys)
#pragma unroll
        for (int n = 0; n < 4; n++) {
            int idx = tid + n * 256;
            int d = idx >> 4, c = idx & 15;
            uint4 vh = *(const uint4*)(sm + PR_AH + d * RSA + c * 16);
            size_t dst = (bb * DO_ + d) * (size_t)LK_ + k0 + c * 8;
            *(uint4*)&ovt[dst] = vh;
        }
    }
}

// ---------------------------------------------------------------------------
// Flash attention: BQ=128, 4 warps (m32 x n64), key-split x2, online softmax,
// QK = bf16 3-term, PV = single fp16 MMA. Fused split-K reduce.
// ---------------------------------------------------------------------------
#define RSTRIDE 144
#define TILE_B  (64 * RSTRIDE)
#define QTILE_B (128 * RSTRIDE)
#define O_QH  0
#define O_QL  QTILE_B
#define O_KV  (2 * QTILE_B)           // 36864
#define KVBUF (3 * TILE_B)            // 27648 (KH, KL, VT)
#define SM_BYTES (O_KV + 2 * KVBUF)   // 92160

__device__ __forceinline__ void kv_load(
    uint32_t dstbase, int tid, int b, int kt,
    const __nv_bfloat16* __restrict__ kh, const __nv_bfloat16* __restrict__ kl,
    const __half* __restrict__ vt)
{
#pragma unroll
    for (int n = 0; n < 12; n++) {
        int i = tid + n * 128;
        int t = i >> 9, r = (i >> 3) & 63, c = i & 7;
        const void* src;
        if (t == 0)      src = kh + ((size_t)b * LK_ + kt + r) * DO_ + c * 8;
        else if (t == 1) src = kl + ((size_t)b * LK_ + kt + r) * DO_ + c * 8;
        else             src = vt + ((size_t)b * DO_ + r) * LK_ + kt + c * 8;
        cp_async16_cg(dstbase + t * TILE_B + r * RSTRIDE + c * 16, src);
    }
}

__global__ __launch_bounds__(128, 2) void attn_mma_kernel(
    const __nv_bfloat16* __restrict__ qh, const __nv_bfloat16* __restrict__ ql,
    const __nv_bfloat16* __restrict__ kh, const __nv_bfloat16* __restrict__ kl,
    const __half* __restrict__ vt,
    float* __restrict__ po, float* __restrict__ pl, float* __restrict__ pm,
    int* __restrict__ flag, float* __restrict__ out)
{
    extern __shared__ __align__(16) char sm[];
    const uint32_t sb = smem_u32(sm);

    const int tid = threadIdx.x;
    const int w = tid >> 5;
    const int lane = tid & 31;
    const int b = blockIdx.y;
    const int ks = blockIdx.z;
    const int it0 = ks * (LK_ / 128);
    const int it1 = it0 + (LK_ / 128);
    const size_t q0 = (size_t)blockIdx.x * 128;
    const int bi = b * (LQ_ / 128) + blockIdx.x;

#pragma unroll
    for (int n = 0; n < 16; n++) {
        int i = tid + n * 128;
        int t = i >> 10, r = (i >> 3) & 127, c = i & 7;
        const __nv_bfloat16* src =
            (t ? ql : qh) + ((size_t)b * LQ_ + q0 + r) * DO_ + c * 8;
        cp_async16(sb + (t ? O_QL : O_QH) + r * RSTRIDE + c * 16, src);
    }
    kv_load(sb + O_KV, tid, b, it0 * 64, kh, kl, vt);
    CP_COMMIT();
    CP_WAIT_ALL();
    __syncthreads();

    uint32_t qfh[2][4][4], qfl[2][4][4];
#pragma unroll
    for (int mi = 0; mi < 2; mi++) {
        int arow = 32 * w + 16 * mi + (lane & 7) + 8 * ((lane >> 3) & 1);
        int acol = 8 * (lane >> 4);
        uint32_t base = (uint32_t)(arow * RSTRIDE + acol * 2);
#pragma unroll
        for (int g = 0; g < 4; g++) {
            ldsm_x4(qfh[mi][g], sb + O_QH + base + 32 * g);
            ldsm_x4(qfl[mi][g], sb + O_QL + base + 32 * g);
        }
    }

    const uint32_t boff = (uint32_t)((lane & 7) * RSTRIDE + (lane >> 3) * 16);

    float oacc[2][8][4];
#pragma unroll
    for (int mi = 0; mi < 2; mi++)
#pragma unroll
        for (int j = 0; j < 8; j++)
#pragma unroll
            for (int c = 0; c < 4; c++) oacc[mi][j][c] = 0.f;
    float lsum[2][2] = {{0.f, 0.f}, {0.f, 0.f}};
    float mrun[2][2] = {{-1e30f, -1e30f}, {-1e30f, -1e30f}};

    for (int it = it0; it < it1; it++) {
        const uint32_t kvb = sb + O_KV + (uint32_t)(it & 1) * KVBUF;
        if (it + 1 < it1) {
            kv_load(sb + O_KV + (uint32_t)((it + 1) & 1) * KVBUF,
                    tid, b, (it + 1) * 64, kh, kl, vt);
            CP_COMMIT();
        }

#pragma unroll 1
        for (int half = 0; half < 2; half++) {
            // ---- S = (Qh+Ql)(Kh+Kl)^T for 32-key half (log2 domain) ----
            float sacc[2][4][4];
#pragma unroll
            for (int mi = 0; mi < 2; mi++)
#pragma unroll
                for (int jj = 0; jj < 4; jj++)
#pragma unroll
                    for (int c = 0; c < 4; c++) sacc[mi][jj][c] = 0.f;

#pragma unroll
            for (int jj = 0; jj < 4; jj++) {
                int j = 4 * half + jj;
                uint32_t bh[8], bl[8];
                uint32_t kb = kvb + j * (8 * RSTRIDE) + boff;
                ldsm_x4(bh, kb);
                ldsm_x4(bh + 4, kb + 64);
                uint32_t lb = kvb + TILE_B + j * (8 * RSTRIDE) + boff;
                ldsm_x4(bl, lb);
                ldsm_x4(bl + 4, lb + 64);
#pragma unroll
                for (int mi = 0; mi < 2; mi++)
#pragma unroll
                    for (int s = 0; s < 4; s++) {
                        mma16816(sacc[mi][jj], qfh[mi][s], bh[2 * s], bh[2 * s + 1]);
                        mma16816(sacc[mi][jj], qfh[mi][s], bl[2 * s], bl[2 * s + 1]);
                        mma16816(sacc[mi][jj], qfl[mi][s], bh[2 * s], bh[2 * s + 1]);
                    }
            }

            // ---- online softmax (log2 domain): p in (0,1] -> fp16 ----
            uint32_t pf[2][2][4];
#pragma unroll
            for (int mi = 0; mi < 2; mi++) {
                float mt0 = sacc[mi][0][0], mt1 = sacc[mi][0][2];
#pragma unroll
                for (int jj = 0; jj < 4; jj++) {
                    mt0 = fmaxf(mt0, fmaxf(sacc[mi][jj][0], sacc[mi][jj][1]));
                    mt1 = fmaxf(mt1, fmaxf(sacc[mi][jj][2], sacc[mi][jj][3]));
                }
                mt0 = fmaxf(mt0, __shfl_xor_sync(0xffffffffu, mt0, 1));
                mt0 = fmaxf(mt0, __shfl_xor_sync(0xffffffffu, mt0, 2));
                mt1 = fmaxf(mt1, __shfl_xor_sync(0xffffffffu, mt1, 1));
                mt1 = fmaxf(mt1, __shfl_xor_sync(0xffffffffu, mt1, 2));
                float mn0 = fmaxf(mrun[mi][0], mt0);
                float mn1 = fmaxf(mrun[mi][1], mt1);
                float sc0 = ex2f(mrun[mi][0] - mn0);
                float sc1 = ex2f(mrun[mi][1] - mn1);
                mrun[mi][0] = mn0;
                mrun[mi][1] = mn1;

                float rs0 = 0.f, rs1 = 0.f;
#pragma unroll
                for (int sg = 0; sg < 2; sg++) {
                    float p0 = ex2f(sacc[mi][2 * sg][0] - mn0);
                    float p1 = ex2f(sacc[mi][2 * sg][1] - mn0);
                    float p2 = ex2f(sacc[mi][2 * sg][2] - mn1);
                    float p3 = ex2f(sacc[mi][2 * sg][3] - mn1);
                    float p4 = ex2f(sacc[mi][2 * sg + 1][0] - mn0);
                    float p5 = ex2f(sacc[mi][2 * sg + 1][1] - mn0);
                    float p6 = ex2f(sacc[mi][2 * sg + 1][2] - mn1);
                    float p7 = ex2f(sacc[mi][2 * sg + 1][3] - mn1);
                    rs0 += (p0 + p1) + (p4 + p5);
                    rs1 += (p2 + p3) + (p6 + p7);
                    pf[mi][sg][0] = pkhf(p0, p1);
                    pf[mi][sg][1] = pkhf(p2, p3);
                    pf[mi][sg][2] = pkhf(p4, p5);
                    pf[mi][sg][3] = pkhf(p6, p7);
                }
                lsum[mi][0] = lsum[mi][0] * sc0 + rs0;
                lsum[mi][1] = lsum[mi][1] * sc1 + rs1;
#pragma unroll
                for (int j = 0; j < 8; j++) {
                    oacc[mi][j][0] *= sc0;
                    oacc[mi][j][1] *= sc0;
                    oacc[mi][j][2] *= sc1;
                    oacc[mi][j][3] *= sc1;
                }
            }

            // ---- O += P(fp16) @ V(fp16): single MMA per (mi,sg,j) ----
#pragma unroll
            for (int j = 0; j < 8; j++) {
                uint32_t vv[4];
                ldsm_x4(vv, kvb + 2 * TILE_B + j * (8 * RSTRIDE) + half * 64 + boff);
#pragma unroll
                for (int mi = 0; mi < 2; mi++)
#pragma unroll
                    for (int sg = 0; sg < 2; sg++)
                        mma16816_f16(oacc[mi][j], pf[mi][sg], vv[2 * sg], vv[2 * sg + 1]);
            }
        }

        CP_WAIT_ALL();
        __syncthreads();
    }

    // ---- write partial O + l + m ----
#pragma unroll
    for (int mi = 0; mi < 2; mi++) {
        float l0 = lsum[mi][0], l1 = lsum[mi][1];
        l0 += __shfl_xor_sync(0xffffffffu, l0, 1);
        l0 += __shfl_xor_sync(0xffffffffu, l0, 2);
        l1 += __shfl_xor_sync(0xffffffffu, l1, 1);
        l1 += __shfl_xor_sync(0xffffffffu, l1, 2);

        int row = 32 * w + 16 * mi + (lane >> 2);
        size_t rg = (size_t)b * LQ_ + q0 + row;
        float* ob = po + ((size_t)ks * NROW + rg) * DO_ + (lane & 3) * 2;
#pragma unroll
        for (int j = 0; j < 8; j++) {
            *(float2*)(ob + 8 * j) = make_float2(oacc[mi][j][0], oacc[mi][j][1]);
            *(float2*)(ob + 8 * j + 8 * DO_) = make_float2(oacc[mi][j][2], oacc[mi][j][3]);
        }
        if ((lane & 3) == 0) {
            pl[(size_t)ks * NROW + rg] = l0;
            pl[(size_t)ks * NROW + rg + 8] = l1;
            pm[(size_t)ks * NROW + rg] = mrun[mi][0];
            pm[(size_t)ks * NROW + rg + 8] = mrun[mi][1];
        }
    }

    // ---- fused reduce: second-arriving CTA combines both key halves ----
    __threadfence();
    __shared__ int s_old;
    __syncthreads();
    if (tid == 0) s_old = atomicAdd(&flag[bi], 1);
    __syncthreads();
    if (s_old == 1) {
        __threadfence();
        const float4* P0 = (const float4*)po;
        const float4* P1 = P0 + (size_t)NROW * DO_ / 4;
#pragma unroll
        for (int n = 0; n < 16; n++) {
            int idx = tid + n * 128;
            int r = idx >> 4, c = idx & 15;
            size_t rg = (size_t)b * LQ_ + q0 + r;
            float m0 = pm[rg], m1 = pm[NROW + rg];
            float ms = fmaxf(m0, m1);
            float sa = ex2f(m0 - ms);
            float sbb = ex2f(m1 - ms);
            float inv = 1.0f / (pl[rg] * sa + pl[NROW + rg] * sbb);
            size_t gi = rg * (DO_ / 4) + c;
            float4 a = P0[gi];
            float4 bb = P1[gi];
            float4 rr = make_float4((a.x * sa + bb.x * sbb) * inv,
                                    (a.y * sa + bb.y * sbb) * inv,
                                    (a.z * sa + bb.z * sbb) * inv,
                                    (a.w * sa + bb.w * sbb) * inv);
            ((float4*)out)[gi] = rr;
        }
        __syncthreads();
        if (tid == 0) flag[bi] = 0;
    }
}

// ---------------------------------------------------------------------------
extern "C" void kernel_launch(void* const* d_in, const int* in_sizes, int n_in,
                              void* d_out, int out_size)
{
    const float* query = (const float*)d_in[0];
    const float* key   = (const float*)d_in[1];
    const float* Wq    = (const float*)d_in[2];
    const float* Wk    = (const float*)d_in[3];
    const float* Wv    = (const float*)d_in[4];
    float* out = (float*)d_out;

    __nv_bfloat16 *qh, *ql, *khp, *klp;
    __half *vt;
    float *po, *pl, *pm;
    int* flag;
    cudaGetSymbolAddress((void**)&qh, g_qh);
    cudaGetSymbolAddress((void**)&ql, g_ql);
    cudaGetSymbolAddress((void**)&khp, g_kh);
    cudaGetSymbolAddress((void**)&klp, g_kl);
    cudaGetSymbolAddress((void**)&vt, g_vt);
    cudaGetSymbolAddress((void**)&po, g_po);
    cudaGetSymbolAddress((void**)&pl, g_pl);
    cudaGetSymbolAddress((void**)&pm, g_pm);
    cudaGetSymbolAddress((void**)&flag, g_flag);

    cudaFuncSetAttribute(proj_mma_kernel,
                         cudaFuncAttributeMaxDynamicSharedMemorySize, PR_SMEM);
    proj_mma_kernel<<<384, 256, PR_SMEM>>>(query, key, Wq, Wk, Wv,
                                           qh, ql, khp, klp, vt);

    cudaFuncSetAttribute(attn_mma_kernel,
                         cudaFuncAttributeMaxDynamicSharedMemorySize, SM_BYTES);
    dim3 grid(LQ_ / 128, B_, 2);
    attn_mma_kernel<<<grid, 128, SM_BYTES>>>(qh, ql, khp, klp, vt,
                                             po, pl, pm, flag, out);
}